// round 1
// baseline (speedup 1.0000x reference)
#include <cuda_runtime.h>
#include <math.h>

#define BATCH 32
#define NPIX  1024
#define CDIM  1024
#define LTOK  16
#define CHALF 512

// ---- scratch offsets (in floats) in one __device__ array ----
#define OF_P     0            // proj / sim logits [B*N*L]   524288
#define OF_T     524288       // T      [B*L*C]              524288
#define OF_TD    1048576      // T_dash [B*L*C]
#define OF_H     1572864      // FFN hidden [B*L*C]
#define OF_K     2097152      // k [B*L*CHALF] 262144
#define OF_Q     2359296      // q [B*L*CHALF] 262144
#define OF_TK    2621440      // Tk [B*L*C] 524288
#define OF_MSIM  3145728      // Msim [B*C*L] 524288
#define OF_B0    3670016      // bias0 [B*L] 512
#define OF_CM    3670528      // col max [B*L]
#define OF_CS    3671040      // col sum [B*L]
#define SCRATCH_TOTAL 3671552

__device__ float g_s[SCRATCH_TOTAL];

// ============================================================
// skinny16: out[b, row, l] = sum_c A[b,row,c] * W[c,l] + bias[l]
// mode 0: W = tok_W (shared), bias = tok_b      (proj stage)
// mode 1: W = Msim[b] (per batch), bias = bias0[b]  (sim stage)
// grid (NPIX/128, BATCH), 256 threads
// ============================================================
__global__ void skinny16_kernel(const float* __restrict__ X,
                                const float* __restrict__ Wext,
                                const float* __restrict__ bext,
                                int mode)
{
    int b = blockIdx.y;
    int rowBase = blockIdx.x * 128;
    const float* A = X + (size_t)b * NPIX * CDIM;
    const float* W;
    const float* bias;
    if (mode == 0) { W = Wext; bias = bext; }
    else {
        W    = &g_s[OF_MSIM + (size_t)b * CDIM * LTOK];
        bias = &g_s[OF_B0 + b * LTOK];
    }
    float* out = &g_s[OF_P + ((size_t)b * NPIX + rowBase) * LTOK];

    __shared__ float As[128][33];
    __shared__ float Ws[32][17];
    int t = threadIdx.x;
    int l = t & 15, rg = t >> 4;
    float acc[8];
#pragma unroll
    for (int i = 0; i < 8; i++) acc[i] = 0.f;

    for (int k0 = 0; k0 < CDIM; k0 += 32) {
#pragma unroll
        for (int i = 0; i < 4; i++) {
            int idx = t + i * 256;
            int r = idx >> 3, kq = idx & 7;
            float4 v = *(const float4*)&A[(size_t)(rowBase + r) * CDIM + k0 + kq * 4];
            As[r][kq * 4 + 0] = v.x; As[r][kq * 4 + 1] = v.y;
            As[r][kq * 4 + 2] = v.z; As[r][kq * 4 + 3] = v.w;
        }
#pragma unroll
        for (int i = 0; i < 2; i++) {
            int idx = t + i * 256;
            int kk = idx >> 4, ll = idx & 15;
            Ws[kk][ll] = W[(k0 + kk) * LTOK + ll];
        }
        __syncthreads();
#pragma unroll
        for (int kk = 0; kk < 32; kk++) {
            float wv = Ws[kk][l];
#pragma unroll
            for (int i = 0; i < 8; i++) acc[i] += As[rg * 8 + i][kk] * wv;
        }
        __syncthreads();
    }
    float bv = bias[l];
#pragma unroll
    for (int i = 0; i < 8; i++) out[(rg * 8 + i) * LTOK + l] = acc[i] + bv;
}

// ============================================================
// softmax stats over pixel dim for tokenizer: per (b,l)
// grid B*L = 512, 128 threads
// ============================================================
__global__ void stats_kernel()
{
    int blk = blockIdx.x;
    int b = blk >> 4, l = blk & 15;
    const float* P = &g_s[OF_P + (size_t)b * NPIX * LTOK + l];
    int t = threadIdx.x;
    __shared__ float red[128];
    float m = -1e30f;
    for (int n = t; n < NPIX; n += 128) m = fmaxf(m, P[n * LTOK]);
    red[t] = m; __syncthreads();
    for (int s = 64; s > 0; s >>= 1) {
        if (t < s) red[t] = fmaxf(red[t], red[t + s]);
        __syncthreads();
    }
    float M = red[0]; __syncthreads();
    float sum = 0.f;
    for (int n = t; n < NPIX; n += 128) sum += __expf(P[n * LTOK] - M);
    red[t] = sum; __syncthreads();
    for (int s = 64; s > 0; s >>= 1) {
        if (t < s) red[t] += red[t + s];
        __syncthreads();
    }
    if (t == 0) { g_s[OF_CM + blk] = M; g_s[OF_CS + blk] = red[0]; }
}

// ============================================================
// T[b,l,c] = sum_n attn[b,n,l] * X[b,n,c]
// grid (CDIM/256, BATCH), 256 threads, each thread owns one c
// ============================================================
__global__ void tok_agg_kernel(const float* __restrict__ X)
{
    int b = blockIdx.y;
    int t = threadIdx.x;
    int c = blockIdx.x * 256 + t;
    __shared__ float mx[16], is[16];
    __shared__ float attnS[64][16];
    if (t < 16) {
        mx[t] = g_s[OF_CM + b * 16 + t];
        is[t] = 1.f / g_s[OF_CS + b * 16 + t];
    }
    __syncthreads();
    float acc[16];
#pragma unroll
    for (int l = 0; l < 16; l++) acc[l] = 0.f;
    const float* P  = &g_s[OF_P + (size_t)b * NPIX * LTOK];
    const float* Xb = X + (size_t)b * NPIX * CDIM;
    for (int n0 = 0; n0 < NPIX; n0 += 64) {
#pragma unroll
        for (int j = 0; j < 4; j++) {
            int idx = t + j * 256;
            int nn = idx >> 4, ll = idx & 15;
            attnS[nn][ll] = __expf(P[(n0 + nn) * LTOK + ll] - mx[ll]) * is[ll];
        }
        __syncthreads();
#pragma unroll 4
        for (int nn = 0; nn < 64; nn++) {
            float x = Xb[(size_t)(n0 + nn) * CDIM + c];
#pragma unroll
            for (int l = 0; l < 16; l++) acc[l] += attnS[nn][l] * x;
        }
        __syncthreads();
    }
    float* T = &g_s[OF_T + (size_t)b * LTOK * CDIM + c];
#pragma unroll
    for (int l = 0; l < 16; l++) T[l * CDIM] = acc[l];
}

// ============================================================
// generic tiled SGEMM: out[M, Ncols] = A[M,1024] @ W[1024,Ncols] + bias
// optional relu, optional residual add (from scratch offset)
// 64x64 tile, 256 threads, 4x4 per thread. M,Ncols multiples of 64.
// ============================================================
__global__ void sgemm_kernel(const float* __restrict__ Aext, int aOff,
                             const float* __restrict__ W,
                             const float* __restrict__ bias,
                             float* __restrict__ outExt, int outOff,
                             int resOff, int Ncols, int relu)
{
    const float* A = Aext ? Aext : &g_s[aOff];
    float* out = outExt ? outExt : &g_s[outOff];
    int col0 = blockIdx.x * 64, row0 = blockIdx.y * 64;
    __shared__ float As[16][68];
    __shared__ float Bs[16][68];
    int t = threadIdx.x, tx = t & 15, ty = t >> 4;
    float acc[4][4];
#pragma unroll
    for (int i = 0; i < 4; i++)
#pragma unroll
        for (int j = 0; j < 4; j++) acc[i][j] = 0.f;

    for (int k0 = 0; k0 < 1024; k0 += 16) {
        {
            int r = t >> 2, kq = t & 3;
            float4 v = *(const float4*)&A[(size_t)(row0 + r) * 1024 + k0 + kq * 4];
            As[kq * 4 + 0][r] = v.x; As[kq * 4 + 1][r] = v.y;
            As[kq * 4 + 2][r] = v.z; As[kq * 4 + 3][r] = v.w;
        }
        {
            int kk = t >> 4, nq = t & 15;
            float4 v = *(const float4*)&W[(size_t)(k0 + kk) * Ncols + col0 + nq * 4];
            *(float4*)&Bs[kk][nq * 4] = v;
        }
        __syncthreads();
#pragma unroll
        for (int kk = 0; kk < 16; kk++) {
            float4 a4 = *(float4*)&As[kk][ty * 4];
            float4 b4 = *(float4*)&Bs[kk][tx * 4];
            float ar[4] = {a4.x, a4.y, a4.z, a4.w};
            float br[4] = {b4.x, b4.y, b4.z, b4.w};
#pragma unroll
            for (int i = 0; i < 4; i++)
#pragma unroll
                for (int j = 0; j < 4; j++) acc[i][j] += ar[i] * br[j];
        }
        __syncthreads();
    }
#pragma unroll
    for (int i = 0; i < 4; i++) {
        int row = row0 + ty * 4 + i;
#pragma unroll
        for (int j = 0; j < 4; j++) {
            int col = col0 + tx * 4 + j;
            float v = acc[i][j] + bias[col];
            if (relu) v = fmaxf(v, 0.f);
            if (resOff >= 0) v += g_s[resOff + (size_t)row * Ncols + col];
            out[(size_t)row * Ncols + col] = v;
        }
    }
}

// ============================================================
// per-batch token attention: scores = k q^T, softmax(axis m),
// T_dash = T + S @ T.  grid BATCH, 256 threads
// ============================================================
__global__ void token_attn_kernel()
{
    int b = blockIdx.x;
    int t = threadIdx.x;
    __shared__ float Ssh[16][17];
    const float* kb = &g_s[OF_K + (size_t)b * LTOK * CHALF];
    const float* qb = &g_s[OF_Q + (size_t)b * LTOK * CHALF];
    {
        int l = t >> 4, m = t & 15;
        const float* kr = kb + l * CHALF;
        const float* qr = qb + m * CHALF;
        float s = 0.f;
        for (int d = 0; d < CHALF; d++) s += kr[d] * qr[d];
        Ssh[l][m] = s;
    }
    __syncthreads();
    if (t < 16) {
        float mvx = -1e30f;
#pragma unroll
        for (int m = 0; m < 16; m++) mvx = fmaxf(mvx, Ssh[t][m]);
        float sum = 0.f;
#pragma unroll
        for (int m = 0; m < 16; m++) { float e = __expf(Ssh[t][m] - mvx); Ssh[t][m] = e; sum += e; }
        float inv = 1.f / sum;
#pragma unroll
        for (int m = 0; m < 16; m++) Ssh[t][m] *= inv;
    }
    __syncthreads();
    const float* T = &g_s[OF_T + (size_t)b * LTOK * CDIM];
    float* Td = &g_s[OF_TD + (size_t)b * LTOK * CDIM];
    for (int c = t; c < CDIM; c += 256) {
        float tv[16];
#pragma unroll
        for (int m = 0; m < 16; m++) tv[m] = T[m * CDIM + c];
#pragma unroll
        for (int l = 0; l < 16; l++) {
            float v = tv[l];
#pragma unroll
            for (int m = 0; m < 16; m++) v += Ssh[l][m] * tv[m];
            Td[l * CDIM + c] = v;
        }
    }
}

// ============================================================
// Msim[b,c',l] = sum_c qW[c',c] * Tk[b,l,c]
// grid (CDIM/128, BATCH), 256 threads
// ============================================================
__global__ void msim_kernel(const float* __restrict__ qW)
{
    int b = blockIdx.y;
    int rowBase = blockIdx.x * 128;   // c'
    const float* Tk = &g_s[OF_TK + (size_t)b * LTOK * CDIM];
    float* out = &g_s[OF_MSIM + (size_t)b * CDIM * LTOK + (size_t)rowBase * LTOK];
    __shared__ float As[128][33];
    __shared__ float Ws[32][17];
    int t = threadIdx.x;
    int l = t & 15, rg = t >> 4;
    float acc[8];
#pragma unroll
    for (int i = 0; i < 8; i++) acc[i] = 0.f;

    for (int k0 = 0; k0 < CDIM; k0 += 32) {
#pragma unroll
        for (int i = 0; i < 4; i++) {
            int idx = t + i * 256;
            int r = idx >> 3, kq = idx & 7;
            float4 v = *(const float4*)&qW[(size_t)(rowBase + r) * CDIM + k0 + kq * 4];
            As[r][kq * 4 + 0] = v.x; As[r][kq * 4 + 1] = v.y;
            As[r][kq * 4 + 2] = v.z; As[r][kq * 4 + 3] = v.w;
        }
#pragma unroll
        for (int i = 0; i < 2; i++) {
            int idx = t + i * 256;                 // < 512
            int kk = idx & 31, ll = idx >> 5;      // coalesced over kk
            Ws[kk][ll] = Tk[ll * CDIM + k0 + kk];
        }
        __syncthreads();
#pragma unroll
        for (int kk = 0; kk < 32; kk++) {
            float wv = Ws[kk][l];
#pragma unroll
            for (int i = 0; i < 8; i++) acc[i] += As[rg * 8 + i][kk] * wv;
        }
        __syncthreads();
    }
#pragma unroll
    for (int i = 0; i < 8; i++) out[(rg * 8 + i) * LTOK + l] = acc[i];
}

// ============================================================
// bias0[b,l] = q_b . Tk[b,l,:]    grid BATCH, 512 threads (16 warps)
// ============================================================
__global__ void bias0_kernel(const float* __restrict__ q_b)
{
    int b = blockIdx.x;
    int w = threadIdx.x >> 5, lane = threadIdx.x & 31;
    const float* Tk = &g_s[OF_TK + ((size_t)b * LTOK + w) * CDIM];
    float s = 0.f;
    for (int c = lane; c < CDIM; c += 32) s += q_b[c] * Tk[c];
#pragma unroll
    for (int o = 16; o > 0; o >>= 1) s += __shfl_xor_sync(0xffffffffu, s, o);
    if (lane == 0) g_s[OF_B0 + b * LTOK + w] = s;
}

// ============================================================
// final: A = softmax(sim, axis=l);  X_out = X + A @ T_out
// T_out read from d_out tail region; T_out[l][c] cached in registers.
// grid (CDIM/256, BATCH), 256 threads
// ============================================================
__global__ void out_kernel(const float* __restrict__ X, float* __restrict__ dout)
{
    int b = blockIdx.y;
    int t = threadIdx.x;
    int c = blockIdx.x * 256 + t;
    const float* Tout = dout + (size_t)BATCH * NPIX * CDIM + (size_t)b * LTOK * CDIM;
    float tout[16];
#pragma unroll
    for (int l = 0; l < 16; l++) tout[l] = Tout[l * CDIM + c];
    __shared__ float As[64][16];
    const float* P  = &g_s[OF_P + (size_t)b * NPIX * LTOK];
    const float* Xb = X + (size_t)b * NPIX * CDIM;
    float* Ob = dout + (size_t)b * NPIX * CDIM;
    for (int n0 = 0; n0 < NPIX; n0 += 64) {
        if (t < 64) {
            const float* pr = &P[(size_t)(n0 + t) * LTOK];
            float v[16];
            float m = -1e30f;
#pragma unroll
            for (int l = 0; l < 16; l++) { v[l] = pr[l]; m = fmaxf(m, v[l]); }
            float s = 0.f;
#pragma unroll
            for (int l = 0; l < 16; l++) { v[l] = __expf(v[l] - m); s += v[l]; }
            float inv = 1.f / s;
#pragma unroll
            for (int l = 0; l < 16; l++) As[t][l] = v[l] * inv;
        }
        __syncthreads();
#pragma unroll 4
        for (int nn = 0; nn < 64; nn++) {
            size_t xi = (size_t)(n0 + nn) * CDIM + c;
            float o = Xb[xi];
#pragma unroll
            for (int l = 0; l < 16; l++) o += As[nn][l] * tout[l];
            Ob[xi] = o;
        }
        __syncthreads();
    }
}

// ============================================================
extern "C" void kernel_launch(void* const* d_in, const int* in_sizes, int n_in,
                              void* d_out, int out_size)
{
    const float* X       = (const float*)d_in[0];
    // d_in[1] = T_in (unused by reference)
    const float* tok_W   = (const float*)d_in[2];
    const float* tok_b   = (const float*)d_in[3];
    const float* key_W   = (const float*)d_in[4];
    const float* key_b   = (const float*)d_in[5];
    const float* query_W = (const float*)d_in[6];
    const float* query_b = (const float*)d_in[7];
    const float* f1_W    = (const float*)d_in[8];
    const float* f1_b    = (const float*)d_in[9];
    const float* f2_W    = (const float*)d_in[10];
    const float* f2_b    = (const float*)d_in[11];
    const float* q_W     = (const float*)d_in[12];
    const float* q_b     = (const float*)d_in[13];
    const float* k_W     = (const float*)d_in[14];
    const float* k_b     = (const float*)d_in[15];
    float* out  = (float*)d_out;
    float* outT = out + (size_t)BATCH * NPIX * CDIM;   // T_out region

    // 1. proj = X @ tok_W + tok_b
    skinny16_kernel<<<dim3(NPIX / 128, BATCH), 256>>>(X, tok_W, tok_b, 0);
    // 2. softmax stats over pixel dim
    stats_kernel<<<BATCH * LTOK, 128>>>();
    // 3. T = attn^T @ X
    tok_agg_kernel<<<dim3(CDIM / 256, BATCH), 256>>>(X);
    // 4/5. k, q projections
    sgemm_kernel<<<dim3(CHALF / 64, (BATCH * LTOK) / 64), 256>>>(nullptr, OF_T, key_W,   key_b,   nullptr, OF_K, -1, CHALF, 0);
    sgemm_kernel<<<dim3(CHALF / 64, (BATCH * LTOK) / 64), 256>>>(nullptr, OF_T, query_W, query_b, nullptr, OF_Q, -1, CHALF, 0);
    // 6. token self-attention + residual
    token_attn_kernel<<<BATCH, 256>>>();
    // 7. FFN1 with relu
    sgemm_kernel<<<dim3(CDIM / 64, (BATCH * LTOK) / 64), 256>>>(nullptr, OF_TD, f1_W, f1_b, nullptr, OF_H, -1, CDIM, 1);
    // 8. FFN2 + residual -> T_out (into d_out tail)
    sgemm_kernel<<<dim3(CDIM / 64, (BATCH * LTOK) / 64), 256>>>(nullptr, OF_H, f2_W, f2_b, outT, 0, OF_TD, CDIM, 0);
    // 9. Tk = T_out @ k_W + k_b
    sgemm_kernel<<<dim3(CDIM / 64, (BATCH * LTOK) / 64), 256>>>(outT, 0, k_W, k_b, nullptr, OF_TK, -1, CDIM, 0);
    // 10. Msim[b] = q_W @ Tk[b]^T
    msim_kernel<<<dim3(CDIM / 128, BATCH), 256>>>(q_W);
    // 11. bias0[b,l] = q_b . Tk[b,l,:]
    bias0_kernel<<<BATCH, 512>>>(q_b);
    // 12. sim = X @ Msim[b] + bias0[b]
    skinny16_kernel<<<dim3(NPIX / 128, BATCH), 256>>>(X, nullptr, nullptr, 1);
    // 13. X_out = X + softmax(sim) @ T_out
    out_kernel<<<dim3(CDIM / 256, BATCH), 256>>>(X, out);
}

// round 4
// speedup vs baseline: 1.8547x; 1.8547x over previous
#include <cuda_runtime.h>
#include <math.h>

#define BATCH 32
#define NPIX  1024
#define CDIM  1024
#define LTOK  16
#define CHALF 512
#define NT    8            // 128-row tiles per batch
#define RPB   128          // rows per block in X-pass kernels

// ---- scratch offsets (floats) ----
// OF_GP (gemm split-K partials, 2M floats) is ALIASED onto OF_U: U is only
// live between k1 and k2; all GEMMs run strictly after k2 on the same stream.
#define OF_U     0                         // [B][NT][16][1024] agg partials (16MB)
#define OF_GP    0                         // alias: split-K partials (2M floats)
#define OF_ZP    4194304                   // [B][NT][16]
#define OF_T     4198400                   // [B][16][1024]
#define OF_TD    4722688
#define OF_H     5246976
#define OF_K     5771264                   // [B*16][512]
#define OF_Q     6033408
#define OF_TK    6295552                   // [B][16][1024]
#define OF_MSIM  6819840                   // [B][1024][16]
#define OF_B0    7344128                   // [B][16]
#define SCRATCH_TOTAL 7344640

__device__ float g_s[SCRATCH_TOTAL];

// ============================================================
// K1: fused tokenizer. Per block: 128 rows of X.
//  A) p = Xrows @ tok_W + tok_b  B) E = exp(p), Zp partial
//  C) U_partial[l,c] = sum_rows E * X
// grid (NT, BATCH), 256 threads
// ============================================================
__global__ __launch_bounds__(256) void k1_token_kernel(const float* __restrict__ X,
                                                       const float* __restrict__ tokW,
                                                       const float* __restrict__ tokB)
{
    int b = blockIdx.y, jt = blockIdx.x;
    const float* Xb = X + ((size_t)b * NPIX + (size_t)jt * RPB) * CDIM;
    __shared__ float As[RPB][33];
    __shared__ float Ws[32][17];
    __shared__ float Esh[RPB][16];
    __shared__ float Zr[16][16];
    int t = threadIdx.x;
    int ks = t >> 7, rem = t & 127, rg = rem >> 3, lg = rem & 7;

    float acc[8][2];
#pragma unroll
    for (int i = 0; i < 8; i++) { acc[i][0] = 0.f; acc[i][1] = 0.f; }

    for (int k0 = 0; k0 < CDIM; k0 += 32) {
#pragma unroll
        for (int i = 0; i < 4; i++) {
            int idx = t + i * 256;
            int r = idx >> 3, kq = idx & 7;
            float4 v = *(const float4*)&Xb[(size_t)r * CDIM + k0 + kq * 4];
            As[r][kq * 4 + 0] = v.x; As[r][kq * 4 + 1] = v.y;
            As[r][kq * 4 + 2] = v.z; As[r][kq * 4 + 3] = v.w;
        }
#pragma unroll
        for (int i = 0; i < 2; i++) {
            int idx = t + i * 256;
            int kk = idx >> 4, ll = idx & 15;
            Ws[kk][ll] = tokW[(k0 + kk) * LTOK + ll];
        }
        __syncthreads();
#pragma unroll
        for (int kk = 0; kk < 16; kk++) {
            int kkk = ks * 16 + kk;
            float w0 = Ws[kkk][lg * 2], w1 = Ws[kkk][lg * 2 + 1];
#pragma unroll
            for (int i = 0; i < 8; i++) {
                float a = As[rg * 8 + i][kkk];
                acc[i][0] += a * w0; acc[i][1] += a * w1;
            }
        }
        __syncthreads();
    }
    if (ks == 1) {
#pragma unroll
        for (int i = 0; i < 8; i++) {
            Esh[rg * 8 + i][lg * 2] = acc[i][0];
            Esh[rg * 8 + i][lg * 2 + 1] = acc[i][1];
        }
    }
    __syncthreads();
    if (ks == 0) {
#pragma unroll
        for (int i = 0; i < 8; i++) {
#pragma unroll
            for (int j = 0; j < 2; j++) {
                int l = lg * 2 + j;
                float p = acc[i][j] + Esh[rg * 8 + i][l] + tokB[l];
                Esh[rg * 8 + i][l] = __expf(p);
            }
        }
    }
    __syncthreads();
    // Zp partial
    {
        int l = t & 15, rgg = t >> 4;
        float s = 0.f;
#pragma unroll
        for (int i = 0; i < 8; i++) s += Esh[rgg * 8 + i][l];
        Zr[rgg][l] = s;
        __syncthreads();
        if (t < 16) {
            float z = 0.f;
#pragma unroll
            for (int g = 0; g < 16; g++) z += Zr[g][t];
            g_s[OF_ZP + (b * NT + jt) * 16 + t] = z;
        }
    }
    __syncthreads();
    // phase C: thread owns c-quad t*4
    float ua[16][4];
#pragma unroll
    for (int l = 0; l < 16; l++)
#pragma unroll
        for (int j = 0; j < 4; j++) ua[l][j] = 0.f;
    const float4* X4 = (const float4*)Xb;
    for (int nn = 0; nn < RPB; nn++) {
        float4 xv = X4[nn * (CDIM / 4) + t];
#pragma unroll
        for (int l = 0; l < 16; l++) {
            float e = Esh[nn][l];
            ua[l][0] += e * xv.x; ua[l][1] += e * xv.y;
            ua[l][2] += e * xv.z; ua[l][3] += e * xv.w;
        }
    }
    float* U = &g_s[OF_U + (((size_t)b * NT + jt) * 16) * CDIM];
#pragma unroll
    for (int l = 0; l < 16; l++)
        *(float4*)&U[(size_t)l * CDIM + t * 4] = make_float4(ua[l][0], ua[l][1], ua[l][2], ua[l][3]);
}

// ============================================================
// K2: reduce partials -> T[b,l,c]. grid (16, B), 256 threads
// ============================================================
__global__ __launch_bounds__(256) void k2_reduce_kernel()
{
    int l = blockIdx.x, b = blockIdx.y;
    int t = threadIdx.x;
    float z = 0.f;
#pragma unroll
    for (int j = 0; j < NT; j++) z += g_s[OF_ZP + (b * NT + j) * 16 + l];
    float inv = 1.f / z;
    float4 s = make_float4(0.f, 0.f, 0.f, 0.f);
#pragma unroll
    for (int j = 0; j < NT; j++) {
        const float4 v = *(const float4*)&g_s[OF_U + (((size_t)b * NT + j) * 16 + l) * CDIM + t * 4];
        s.x += v.x; s.y += v.y; s.z += v.z; s.w += v.w;
    }
    s.x *= inv; s.y *= inv; s.z *= inv; s.w *= inv;
    *(float4*)&g_s[OF_T + ((size_t)b * 16 + l) * CDIM + t * 4] = s;
}

// ============================================================
// split-K GEMM partials: part[s] = A[512, kslice] @ W[kslice, N]
// grid (N/64, 8, Z): Z=4 single W, Z=8 dual (z>>2 selects W/out)
// ============================================================
__global__ __launch_bounds__(256) void gemm_part_kernel(
    const float* __restrict__ Aext, int aOff,
    const float* __restrict__ W1, const float* __restrict__ W2,
    int pOff1, int pOff2, int Ncols)
{
    const float* A = Aext ? Aext : &g_s[aOff];
    int which = blockIdx.z >> 2;
    const float* W = which ? W2 : W1;
    int s = blockIdx.z & 3;
    float* part = &g_s[which ? pOff2 : pOff1] + (size_t)s * 512 * Ncols;
    int col0 = blockIdx.x * 64, row0 = blockIdx.y * 64;
    __shared__ float As[16][68];
    __shared__ float Bs[16][68];
    int t = threadIdx.x, tx = t & 15, ty = t >> 4;
    float acc[4][4];
#pragma unroll
    for (int i = 0; i < 4; i++)
#pragma unroll
        for (int j = 0; j < 4; j++) acc[i][j] = 0.f;

    int kbeg = s * 256;
    for (int k0 = kbeg; k0 < kbeg + 256; k0 += 16) {
        {
            int r = t >> 2, kq = t & 3;
            float4 v = *(const float4*)&A[(size_t)(row0 + r) * 1024 + k0 + kq * 4];
            As[kq * 4 + 0][r] = v.x; As[kq * 4 + 1][r] = v.y;
            As[kq * 4 + 2][r] = v.z; As[kq * 4 + 3][r] = v.w;
        }
        {
            int kk = t >> 4, nq = t & 15;
            float4 v = *(const float4*)&W[(size_t)(k0 + kk) * Ncols + col0 + nq * 4];
            *(float4*)&Bs[kk][nq * 4] = v;
        }
        __syncthreads();
#pragma unroll
        for (int kk = 0; kk < 16; kk++) {
            float4 a4 = *(float4*)&As[kk][ty * 4];
            float4 b4 = *(float4*)&Bs[kk][tx * 4];
            float ar[4] = {a4.x, a4.y, a4.z, a4.w};
            float br[4] = {b4.x, b4.y, b4.z, b4.w};
#pragma unroll
            for (int i = 0; i < 4; i++)
#pragma unroll
                for (int j = 0; j < 4; j++) acc[i][j] += ar[i] * br[j];
        }
        __syncthreads();
    }
#pragma unroll
    for (int i = 0; i < 4; i++) {
        int row = row0 + ty * 4 + i;
#pragma unroll
        for (int j = 0; j < 4; j++)
            part[(size_t)row * Ncols + col0 + tx * 4 + j] = acc[i][j];
    }
}

// ============================================================
// GEMM epilogue: out = sum_s part[s] + bias (+relu) (+res)
// grid 512*N/1024, 256 threads, float4
// ============================================================
__global__ __launch_bounds__(256) void gemm_epi_kernel(int pOff, const float* __restrict__ bias,
                                float* __restrict__ outExt, int outOff, int resOff,
                                int Ncols, int relu)
{
    int idx = blockIdx.x * 256 + threadIdx.x;
    int c4 = idx % (Ncols / 4);
    const float4* P4 = (const float4*)&g_s[pOff];
    int stride = 512 * (Ncols / 4);
    float4 v = P4[idx];
#pragma unroll
    for (int s = 1; s < 4; s++) {
        float4 p = P4[s * stride + idx];
        v.x += p.x; v.y += p.y; v.z += p.z; v.w += p.w;
    }
    float4 bb = *(const float4*)&bias[c4 * 4];
    v.x += bb.x; v.y += bb.y; v.z += bb.z; v.w += bb.w;
    if (relu) {
        v.x = fmaxf(v.x, 0.f); v.y = fmaxf(v.y, 0.f);
        v.z = fmaxf(v.z, 0.f); v.w = fmaxf(v.w, 0.f);
    }
    if (resOff >= 0) {
        float4 r = ((const float4*)&g_s[resOff])[idx];
        v.x += r.x; v.y += r.y; v.z += r.z; v.w += r.w;
    }
    float4* out = outExt ? (float4*)outExt : (float4*)&g_s[outOff];
    out[idx] = v;
}

// ============================================================
// per-batch token attention: scores = k q^T, softmax over m,
// T_dash = T + S @ T.  grid BATCH, 256 threads
// ============================================================
__global__ __launch_bounds__(256) void token_attn_kernel()
{
    int b = blockIdx.x;
    int t = threadIdx.x;
    __shared__ float Ssh[16][17];
    const float* kb = &g_s[OF_K + (size_t)b * LTOK * CHALF];
    const float* qb = &g_s[OF_Q + (size_t)b * LTOK * CHALF];
    {
        int l = t >> 4, m = t & 15;
        const float* kr = kb + l * CHALF;
        const float* qr = qb + m * CHALF;
        float s = 0.f;
#pragma unroll 8
        for (int d = 0; d < CHALF; d++) s += kr[d] * qr[d];
        Ssh[l][m] = s;
    }
    __syncthreads();
    if (t < 16) {
        float mvx = -1e30f;
#pragma unroll
        for (int m = 0; m < 16; m++) mvx = fmaxf(mvx, Ssh[t][m]);
        float sum = 0.f;
#pragma unroll
        for (int m = 0; m < 16; m++) { float e = __expf(Ssh[t][m] - mvx); Ssh[t][m] = e; sum += e; }
        float inv = 1.f / sum;
#pragma unroll
        for (int m = 0; m < 16; m++) Ssh[t][m] *= inv;
    }
    __syncthreads();
    const float* T = &g_s[OF_T + (size_t)b * LTOK * CDIM];
    float* Td = &g_s[OF_TD + (size_t)b * LTOK * CDIM];
    for (int c = t; c < CDIM; c += 256) {
        float tv[16];
#pragma unroll
        for (int m = 0; m < 16; m++) tv[m] = T[m * CDIM + c];
#pragma unroll
        for (int l = 0; l < 16; l++) {
            float v = tv[l];
#pragma unroll
            for (int m = 0; m < 16; m++) v += Ssh[l][m] * tv[m];
            Td[l * CDIM + c] = v;
        }
    }
}

// ============================================================
// Msim[b,c',l] = sum_c qW[c',c] * Tk[b,l,c]
// grid (8, BATCH), 256 threads, K1-phase-A style tiling
// ============================================================
__global__ __launch_bounds__(256) void msim_kernel(const float* __restrict__ qW)
{
    int b = blockIdx.y;
    int rowBase = blockIdx.x * RPB;
    const float* Tk = &g_s[OF_TK + (size_t)b * LTOK * CDIM];
    float* out = &g_s[OF_MSIM + (size_t)b * CDIM * LTOK + (size_t)rowBase * LTOK];
    __shared__ float As[RPB][33];
    __shared__ float Ws[32][17];
    __shared__ float Psh[RPB][16];
    int t = threadIdx.x;
    int ks = t >> 7, rem = t & 127, rg = rem >> 3, lg = rem & 7;
    float acc[8][2];
#pragma unroll
    for (int i = 0; i < 8; i++) { acc[i][0] = 0.f; acc[i][1] = 0.f; }

    for (int k0 = 0; k0 < CDIM; k0 += 32) {
#pragma unroll
        for (int i = 0; i < 4; i++) {
            int idx = t + i * 256;
            int r = idx >> 3, kq = idx & 7;
            float4 v = *(const float4*)&qW[(size_t)(rowBase + r) * CDIM + k0 + kq * 4];
            As[r][kq * 4 + 0] = v.x; As[r][kq * 4 + 1] = v.y;
            As[r][kq * 4 + 2] = v.z; As[r][kq * 4 + 3] = v.w;
        }
#pragma unroll
        for (int i = 0; i < 2; i++) {
            int idx = t + i * 256;
            int kk = idx & 31, ll = idx >> 5;
            Ws[kk][ll] = Tk[ll * CDIM + k0 + kk];
        }
        __syncthreads();
#pragma unroll
        for (int kk = 0; kk < 16; kk++) {
            int kkk = ks * 16 + kk;
            float w0 = Ws[kkk][lg * 2], w1 = Ws[kkk][lg * 2 + 1];
#pragma unroll
            for (int i = 0; i < 8; i++) {
                float a = As[rg * 8 + i][kkk];
                acc[i][0] += a * w0; acc[i][1] += a * w1;
            }
        }
        __syncthreads();
    }
    if (ks == 1) {
#pragma unroll
        for (int i = 0; i < 8; i++) {
            Psh[rg * 8 + i][lg * 2] = acc[i][0];
            Psh[rg * 8 + i][lg * 2 + 1] = acc[i][1];
        }
    }
    __syncthreads();
    if (ks == 0) {
#pragma unroll
        for (int i = 0; i < 8; i++) {
#pragma unroll
            for (int j = 0; j < 2; j++) {
                int l = lg * 2 + j;
                out[(rg * 8 + i) * LTOK + l] = acc[i][j] + Psh[rg * 8 + i][l];
            }
        }
    }
}

// ============================================================
// bias0[b,l] = q_b . Tk[b,l,:]    grid BATCH, 512 threads
// ============================================================
__global__ __launch_bounds__(512) void bias0_kernel(const float* __restrict__ q_b)
{
    int b = blockIdx.x;
    int w = threadIdx.x >> 5, lane = threadIdx.x & 31;
    const float* Tk = &g_s[OF_TK + ((size_t)b * LTOK + w) * CDIM];
    float s = 0.f;
    for (int c = lane; c < CDIM; c += 32) s += q_b[c] * Tk[c];
#pragma unroll
    for (int o = 16; o > 0; o >>= 1) s += __shfl_xor_sync(0xffffffffu, s, o);
    if (lane == 0) g_s[OF_B0 + b * LTOK + w] = s;
}

// ============================================================
// K10: fused projector. Per block 128 rows:
//  A) sim = Xrows @ Msim[b] + bias0  B) softmax over 16 (local)
//  C) X_out = Xrows + A @ T_out (T_out in regs)
// grid (NT, BATCH), 256 threads
// ============================================================
__global__ __launch_bounds__(256) void k10_out_kernel(const float* __restrict__ X,
                                                      float* __restrict__ dout)
{
    int b = blockIdx.y, jt = blockIdx.x;
    const float* Xb = X + ((size_t)b * NPIX + (size_t)jt * RPB) * CDIM;
    __shared__ float As[RPB][33];
    __shared__ float Ws[32][17];
    __shared__ float Ssh[RPB][16];
    int t = threadIdx.x;
    int ks = t >> 7, rem = t & 127, rg = rem >> 3, lg = rem & 7;
    const float* M = &g_s[OF_MSIM + (size_t)b * CDIM * LTOK];

    float acc[8][2];
#pragma unroll
    for (int i = 0; i < 8; i++) { acc[i][0] = 0.f; acc[i][1] = 0.f; }

    for (int k0 = 0; k0 < CDIM; k0 += 32) {
#pragma unroll
        for (int i = 0; i < 4; i++) {
            int idx = t + i * 256;
            int r = idx >> 3, kq = idx & 7;
            float4 v = *(const float4*)&Xb[(size_t)r * CDIM + k0 + kq * 4];
            As[r][kq * 4 + 0] = v.x; As[r][kq * 4 + 1] = v.y;
            As[r][kq * 4 + 2] = v.z; As[r][kq * 4 + 3] = v.w;
        }
#pragma unroll
        for (int i = 0; i < 2; i++) {
            int idx = t + i * 256;
            int kk = idx >> 4, ll = idx & 15;
            Ws[kk][ll] = M[(k0 + kk) * LTOK + ll];
        }
        __syncthreads();
#pragma unroll
        for (int kk = 0; kk < 16; kk++) {
            int kkk = ks * 16 + kk;
            float w0 = Ws[kkk][lg * 2], w1 = Ws[kkk][lg * 2 + 1];
#pragma unroll
            for (int i = 0; i < 8; i++) {
                float a = As[rg * 8 + i][kkk];
                acc[i][0] += a * w0; acc[i][1] += a * w1;
            }
        }
        __syncthreads();
    }
    if (ks == 1) {
#pragma unroll
        for (int i = 0; i < 8; i++) {
            Ssh[rg * 8 + i][lg * 2] = acc[i][0];
            Ssh[rg * 8 + i][lg * 2 + 1] = acc[i][1];
        }
    }
    __syncthreads();
    if (ks == 0) {
#pragma unroll
        for (int i = 0; i < 8; i++) {
#pragma unroll
            for (int j = 0; j < 2; j++) {
                int l = lg * 2 + j;
                Ssh[rg * 8 + i][l] = acc[i][j] + Ssh[rg * 8 + i][l] + g_s[OF_B0 + b * LTOK + l];
            }
        }
    }
    __syncthreads();
    // phase B: per-row softmax over 16
    if (t < RPB) {
        float v[16];
        float m = -1e30f;
#pragma unroll
        for (int l = 0; l < 16; l++) { v[l] = Ssh[t][l]; m = fmaxf(m, v[l]); }
        float s = 0.f;
#pragma unroll
        for (int l = 0; l < 16; l++) { v[l] = __expf(v[l] - m); s += v[l]; }
        float inv = 1.f / s;
#pragma unroll
        for (int l = 0; l < 16; l++) Ssh[t][l] = v[l] * inv;
    }
    __syncthreads();
    // T_out into registers: thread owns c-quad t*4
    const float* Tout = dout + (size_t)BATCH * NPIX * CDIM + (size_t)b * LTOK * CDIM;
    float4 tv[16];
#pragma unroll
    for (int l = 0; l < 16; l++) tv[l] = *(const float4*)&Tout[(size_t)l * CDIM + t * 4];
    // phase C
    const float4* X4 = (const float4*)Xb;
    float4* O4 = (float4*)(dout + ((size_t)b * NPIX + (size_t)jt * RPB) * CDIM);
    for (int nn = 0; nn < RPB; nn++) {
        float4 o = X4[nn * (CDIM / 4) + t];
#pragma unroll
        for (int l = 0; l < 16; l++) {
            float a = Ssh[nn][l];
            o.x += a * tv[l].x; o.y += a * tv[l].y;
            o.z += a * tv[l].z; o.w += a * tv[l].w;
        }
        O4[nn * (CDIM / 4) + t] = o;
    }
}

// ============================================================
extern "C" void kernel_launch(void* const* d_in, const int* in_sizes, int n_in,
                              void* d_out, int out_size)
{
    const float* X       = (const float*)d_in[0];
    const float* tok_W   = (const float*)d_in[2];
    const float* tok_b   = (const float*)d_in[3];
    const float* key_W   = (const float*)d_in[4];
    const float* key_b   = (const float*)d_in[5];
    const float* query_W = (const float*)d_in[6];
    const float* query_b = (const float*)d_in[7];
    const float* f1_W    = (const float*)d_in[8];
    const float* f1_b    = (const float*)d_in[9];
    const float* f2_W    = (const float*)d_in[10];
    const float* f2_b    = (const float*)d_in[11];
    const float* q_W     = (const float*)d_in[12];
    const float* q_b     = (const float*)d_in[13];
    const float* k_W     = (const float*)d_in[14];
    const float* k_b     = (const float*)d_in[15];
    float* out  = (float*)d_out;
    float* outT = out + (size_t)BATCH * NPIX * CDIM;

    // 1. fused tokenizer (proj + exp + partial aggregate)
    k1_token_kernel<<<dim3(NT, BATCH), 256>>>(X, tok_W, tok_b);
    // 2. reduce partials -> T  (consumes OF_U; OF_GP may alias it afterwards)
    k2_reduce_kernel<<<dim3(16, BATCH), 256>>>();
    // 3. k and q projections (fused, split-K4)
    gemm_part_kernel<<<dim3(8, 8, 8), 256>>>(nullptr, OF_T, key_W, query_W,
                                             OF_GP, OF_GP + 4 * 512 * 512, CHALF);
    gemm_epi_kernel<<<256, 256>>>(OF_GP, key_b, nullptr, OF_K, -1, CHALF, 0);
    gemm_epi_kernel<<<256, 256>>>(OF_GP + 4 * 512 * 512, query_b, nullptr, OF_Q, -1, CHALF, 0);
    // 4. token self-attention + residual
    token_attn_kernel<<<BATCH, 256>>>();
    // 5. FFN1 (relu)
    gemm_part_kernel<<<dim3(16, 8, 4), 256>>>(nullptr, OF_TD, f1_W, nullptr, OF_GP, OF_GP, CDIM);
    gemm_epi_kernel<<<512, 256>>>(OF_GP, f1_b, nullptr, OF_H, -1, CDIM, 1);
    // 6. FFN2 + residual -> T_out (d_out tail)
    gemm_part_kernel<<<dim3(16, 8, 4), 256>>>(nullptr, OF_H, f2_W, nullptr, OF_GP, OF_GP, CDIM);
    gemm_epi_kernel<<<512, 256>>>(OF_GP, f2_b, outT, 0, OF_TD, CDIM, 0);
    // 7. Tk = T_out @ k_W + k_b
    gemm_part_kernel<<<dim3(16, 8, 4), 256>>>(outT, 0, k_W, nullptr, OF_GP, OF_GP, CDIM);
    gemm_epi_kernel<<<512, 256>>>(OF_GP, k_b, nullptr, OF_TK, -1, CDIM, 0);
    // 8. Msim[b] = q_W @ Tk[b]^T
    msim_kernel<<<dim3(NT, BATCH), 256>>>(q_W);
    // 9. bias0
    bias0_kernel<<<BATCH, 512>>>(q_b);
    // 10. fused sim + softmax + X_out
    k10_out_kernel<<<dim3(NT, BATCH), 256>>>(X, out);
}